// round 12
// baseline (speedup 1.0000x reference)
#include <cuda_runtime.h>

// ---------------------------------------------------------------------------
// JLoss: j[b] = -sum_{i!=k} log(0.5 + 0.5*(S[b,i,i] - S[b,i,k]))
//   where S[b,i,k] = (sum over pixels p with target[b,p]==k of pred[b,i,p]) / n_k[b]
//
// Plan:
//   k_zero  : zero scratch T (B*C*C) and n (B*C)
//   k_hist  : n[b,k] = pixel count of class k in batch b
//   k_main  : T[b,i,k] via tiled, lane==channel segmented reduction
//   k_final : epilogue (logf + reduction) -> out[b]
// ---------------------------------------------------------------------------

#define C32   32
#define TILE  256
#define NW    8        // warps per block
#define TPB   256      // threads per block (main kernel)

// scratch (no cudaMalloc allowed)
__device__ float g_T[65536];   // B*C*C <= 8192 used
__device__ int   g_n[4096];    // B*C   <= 256 used

// shared layout (dynamic):
//   float s_tile[32][TILE+1]   : 32*257*4 = 32896 B
//   float s_acc [NW][32][32]   : 8*1024*4 = 32768 B
//   int   s_targ[TILE]         : 1024 B
#define SM_TILE_F   (32 * (TILE + 1))
#define SM_ACC_F    (NW * 32 * 32)
#define SMEM_BYTES  ((SM_TILE_F + SM_ACC_F) * 4 + TILE * 4)

__global__ void k_zero(int nT, int nN) {
    int i = blockIdx.x * blockDim.x + threadIdx.x;
    int stride = gridDim.x * blockDim.x;
    for (int x = i; x < nT; x += stride) g_T[x] = 0.0f;
    for (int x = i; x < nN; x += stride) g_n[x] = 0;
}

__global__ void k_hist(const int* __restrict__ targ, int HW) {
    __shared__ int h[C32];
    int b = blockIdx.y;
    if (threadIdx.x < C32) h[threadIdx.x] = 0;
    __syncthreads();
    int stride = gridDim.x * blockDim.x;
    for (int p = blockIdx.x * blockDim.x + threadIdx.x; p < HW; p += stride) {
        int k = targ[(size_t)b * HW + p];
        atomicAdd(&h[k], 1);
    }
    __syncthreads();
    if (threadIdx.x < C32) atomicAdd(&g_n[b * C32 + threadIdx.x], h[threadIdx.x]);
}

__device__ __forceinline__ void flush_acc(const float* s_acc, int b, int tid) {
    // s_acc[w][k][i] ; T layout: g_T[b*C*C + i*C + k]
    for (int kk = tid; kk < C32 * C32; kk += TPB) {
        float s = 0.0f;
        #pragma unroll
        for (int w = 0; w < NW; ++w) s += s_acc[w * (C32 * C32) + kk];
        int k = kk >> 5;
        int i = kk & 31;
        atomicAdd(&g_T[b * (C32 * C32) + i * C32 + k], s);
    }
}

__global__ void __launch_bounds__(TPB, 3)
k_main(const float* __restrict__ pred, const int* __restrict__ targ,
       int B, int HW, int tilesPerBatch) {
    extern __shared__ float sm[];
    float* s_tile = sm;                       // [32][TILE+1]
    float* s_acc  = sm + SM_TILE_F;           // [NW][32][32]
    int*   s_targ = (int*)(sm + SM_TILE_F + SM_ACC_F);  // [TILE]

    const int tid  = threadIdx.x;
    const int w    = tid >> 5;
    const int lane = tid & 31;

    // balanced contiguous tile chunks
    const int total = B * tilesPerBatch;
    const int G = gridDim.x;
    const int q = total / G, r = total % G;
    const int bi = blockIdx.x;
    const int t0 = bi * q + (bi < r ? bi : r);
    const int t1 = t0 + q + (bi < r ? 1 : 0);

    float* trow = s_tile + lane * (TILE + 1);       // this lane's channel row
    float* accw = s_acc + w * (C32 * C32) + lane;   // index by k*32

    int curb = -1;
    for (int t = t0; t < t1; ++t) {
        int b    = t / tilesPerBatch;
        int tile = t - b * tilesPerBatch;

        if (b != curb) {
            if (curb >= 0) {
                flush_acc(s_acc, curb, tid);
                __syncthreads();
            }
            for (int z = tid; z < NW * C32 * C32; z += TPB) s_acc[z] = 0.0f;
            curb = b;
        }

        const int p0 = tile * TILE;
        // stage target
        {
            int p = p0 + tid;
            s_targ[tid] = (p < HW) ? targ[(size_t)b * HW + p] : 0;
        }
        // stage pred tile: iteration c loads channel c, pixel tid (coalesced)
        const float* pb = pred + (size_t)b * C32 * HW + p0;
        if (p0 + TILE <= HW) {
            #pragma unroll 8
            for (int c = 0; c < C32; ++c)
                s_tile[c * (TILE + 1) + tid] = pb[(size_t)c * HW + tid];
        } else {
            int p = p0 + tid;
            #pragma unroll 8
            for (int c = 0; c < C32; ++c)
                s_tile[c * (TILE + 1) + tid] = (p < HW) ? pb[(size_t)c * HW + tid] : 0.0f;
        }
        __syncthreads();

        // warp w handles pixels [w*32, w*32+32); lane == channel
        const int jbase = w * 32;
        const int4* st4 = (const int4*)s_targ;
        #pragma unroll
        for (int qq = 0; qq < 8; ++qq) {
            int4 k4 = st4[(jbase >> 2) + qq];      // broadcast LDS.128
            float v0 = trow[jbase + 4 * qq + 0];
            float v1 = trow[jbase + 4 * qq + 1];
            float v2 = trow[jbase + 4 * qq + 2];
            float v3 = trow[jbase + 4 * qq + 3];
            accw[k4.x * 32] += v0;                 // conflict-free: bank == lane
            accw[k4.y * 32] += v1;
            accw[k4.z * 32] += v2;
            accw[k4.w * 32] += v3;
        }
        __syncthreads();
    }
    if (curb >= 0) flush_acc(s_acc, curb, tid);
}

__global__ void k_final(float* __restrict__ out) {
    const int b   = blockIdx.x;
    const int tid = threadIdx.x;          // 1024 threads
    const int i = tid >> 5;               // warp id
    const int k = tid & 31;               // lane

    __shared__ float s_diag[C32];
    __shared__ float s_red[C32];

    float nk = (float)g_n[b * C32 + k];
    float S  = g_T[b * (C32 * C32) + i * C32 + k] / nk;
    if (i == k) s_diag[i] = S;
    __syncthreads();

    float term = (i != k) ? logf(0.5f + 0.5f * (s_diag[i] - S)) : 0.0f;
    #pragma unroll
    for (int o = 16; o > 0; o >>= 1)
        term += __shfl_down_sync(0xFFFFFFFFu, term, o);
    if (k == 0) s_red[i] = term;
    __syncthreads();
    if (tid < 32) {
        float v = s_red[tid];
        #pragma unroll
        for (int o = 16; o > 0; o >>= 1)
            v += __shfl_down_sync(0xFFFFFFFFu, v, o);
        if (tid == 0) out[b] = -v;
    }
}

extern "C" void kernel_launch(void* const* d_in, const int* in_sizes, int n_in,
                              void* d_out, int out_size) {
    const float* pred = (const float*)d_in[0];
    const int*   targ = (const int*)d_in[1];
    float*       out  = (float*)d_out;

    const int B  = out_size;                   // j is (B,)
    const int HW = in_sizes[1] / B;            // target is (B,H,W)
    // C = in_sizes[0] / in_sizes[1] == 32 for this problem (design assumes 32)

    const int tilesPerBatch = (HW + TILE - 1) / TILE;
    const int total = B * tilesPerBatch;

    cudaFuncSetAttribute(k_main, cudaFuncAttributeMaxDynamicSharedMemorySize,
                         SMEM_BYTES);

    k_zero<<<4, 256>>>(B * C32 * C32, B * C32);

    dim3 hg(64, B);
    k_hist<<<hg, 256>>>(targ, HW);

    int grid = 444;                            // 148 SMs * 3 blocks
    if (grid > total) grid = total;
    k_main<<<grid, TPB, SMEM_BYTES>>>(pred, targ, B, HW, tilesPerBatch);

    k_final<<<B, C32 * C32>>>(out);
}

// round 13
// speedup vs baseline: 1.0039x; 1.0039x over previous
#include <cuda_runtime.h>

// ---------------------------------------------------------------------------
// JLoss: j[b] = -sum_{i!=k} log(0.5 + 0.5*(S[b,i,i] - S[b,i,k]))
//   where S[b,i,k] = (sum over pixels p with target[b,p]==k of pred[b,i,p]) / n_k[b]
//
// Plan:
//   k_zero  : zero scratch T (B*C*C) and n (B*C)
//   k_hist  : n[b,k] = pixel count of class k in batch b
//   k_main  : T[b,i,k] via tiled, lane==channel segmented reduction
//   k_final : epilogue (logf + reduction) -> out[b]
// ---------------------------------------------------------------------------

#define C32   32
#define TILE  256
#define NW    8        // warps per block
#define TPB   256      // threads per block (main kernel)

// scratch (no cudaMalloc allowed)
__device__ float g_T[65536];   // B*C*C <= 8192 used
__device__ int   g_n[4096];    // B*C   <= 256 used

// shared layout (dynamic):
//   float s_tile[32][TILE+1]   : 32*257*4 = 32896 B
//   float s_acc [NW][32][32]   : 8*1024*4 = 32768 B
//   int   s_targ[TILE]         : 1024 B
#define SM_TILE_F   (32 * (TILE + 1))
#define SM_ACC_F    (NW * 32 * 32)
#define SMEM_BYTES  ((SM_TILE_F + SM_ACC_F) * 4 + TILE * 4)

__global__ void k_zero(int nT, int nN) {
    int i = blockIdx.x * blockDim.x + threadIdx.x;
    int stride = gridDim.x * blockDim.x;
    for (int x = i; x < nT; x += stride) g_T[x] = 0.0f;
    for (int x = i; x < nN; x += stride) g_n[x] = 0;
}

__global__ void k_hist(const int* __restrict__ targ, int HW) {
    __shared__ int h[C32];
    int b = blockIdx.y;
    if (threadIdx.x < C32) h[threadIdx.x] = 0;
    __syncthreads();
    int stride = gridDim.x * blockDim.x;
    for (int p = blockIdx.x * blockDim.x + threadIdx.x; p < HW; p += stride) {
        int k = targ[(size_t)b * HW + p];
        atomicAdd(&h[k], 1);
    }
    __syncthreads();
    if (threadIdx.x < C32) atomicAdd(&g_n[b * C32 + threadIdx.x], h[threadIdx.x]);
}

__device__ __forceinline__ void flush_acc(const float* s_acc, int b, int tid) {
    // s_acc[w][k][i] ; T layout: g_T[b*C*C + i*C + k]
    for (int kk = tid; kk < C32 * C32; kk += TPB) {
        float s = 0.0f;
        #pragma unroll
        for (int w = 0; w < NW; ++w) s += s_acc[w * (C32 * C32) + kk];
        int k = kk >> 5;
        int i = kk & 31;
        atomicAdd(&g_T[b * (C32 * C32) + i * C32 + k], s);
    }
}

__global__ void __launch_bounds__(TPB, 3)
k_main(const float* __restrict__ pred, const int* __restrict__ targ,
       int B, int HW, int tilesPerBatch) {
    extern __shared__ float sm[];
    float* s_tile = sm;                       // [32][TILE+1]
    float* s_acc  = sm + SM_TILE_F;           // [NW][32][32]
    int*   s_targ = (int*)(sm + SM_TILE_F + SM_ACC_F);  // [TILE]

    const int tid  = threadIdx.x;
    const int w    = tid >> 5;
    const int lane = tid & 31;

    // balanced contiguous tile chunks
    const int total = B * tilesPerBatch;
    const int G = gridDim.x;
    const int q = total / G, r = total % G;
    const int bi = blockIdx.x;
    const int t0 = bi * q + (bi < r ? bi : r);
    const int t1 = t0 + q + (bi < r ? 1 : 0);

    float* trow = s_tile + lane * (TILE + 1);       // this lane's channel row
    float* accw = s_acc + w * (C32 * C32) + lane;   // index by k*32

    int curb = -1;
    for (int t = t0; t < t1; ++t) {
        int b    = t / tilesPerBatch;
        int tile = t - b * tilesPerBatch;

        if (b != curb) {
            if (curb >= 0) {
                flush_acc(s_acc, curb, tid);
                __syncthreads();
            }
            for (int z = tid; z < NW * C32 * C32; z += TPB) s_acc[z] = 0.0f;
            curb = b;
        }

        const int p0 = tile * TILE;
        // stage target
        {
            int p = p0 + tid;
            s_targ[tid] = (p < HW) ? targ[(size_t)b * HW + p] : 0;
        }
        // stage pred tile: iteration c loads channel c, pixel tid (coalesced)
        const float* pb = pred + (size_t)b * C32 * HW + p0;
        if (p0 + TILE <= HW) {
            #pragma unroll 8
            for (int c = 0; c < C32; ++c)
                s_tile[c * (TILE + 1) + tid] = pb[(size_t)c * HW + tid];
        } else {
            int p = p0 + tid;
            #pragma unroll 8
            for (int c = 0; c < C32; ++c)
                s_tile[c * (TILE + 1) + tid] = (p < HW) ? pb[(size_t)c * HW + tid] : 0.0f;
        }
        __syncthreads();

        // warp w handles pixels [w*32, w*32+32); lane == channel
        const int jbase = w * 32;
        const int4* st4 = (const int4*)s_targ;
        #pragma unroll
        for (int qq = 0; qq < 8; ++qq) {
            int4 k4 = st4[(jbase >> 2) + qq];      // broadcast LDS.128
            float v0 = trow[jbase + 4 * qq + 0];
            float v1 = trow[jbase + 4 * qq + 1];
            float v2 = trow[jbase + 4 * qq + 2];
            float v3 = trow[jbase + 4 * qq + 3];
            accw[k4.x * 32] += v0;                 // conflict-free: bank == lane
            accw[k4.y * 32] += v1;
            accw[k4.z * 32] += v2;
            accw[k4.w * 32] += v3;
        }
        __syncthreads();
    }
    if (curb >= 0) flush_acc(s_acc, curb, tid);
}

__global__ void k_final(float* __restrict__ out) {
    const int b   = blockIdx.x;
    const int tid = threadIdx.x;          // 1024 threads
    const int i = tid >> 5;               // warp id
    const int k = tid & 31;               // lane

    __shared__ float s_diag[C32];
    __shared__ float s_red[C32];

    float nk = (float)g_n[b * C32 + k];
    float S  = g_T[b * (C32 * C32) + i * C32 + k] / nk;
    if (i == k) s_diag[i] = S;
    __syncthreads();

    float term = (i != k) ? logf(0.5f + 0.5f * (s_diag[i] - S)) : 0.0f;
    #pragma unroll
    for (int o = 16; o > 0; o >>= 1)
        term += __shfl_down_sync(0xFFFFFFFFu, term, o);
    if (k == 0) s_red[i] = term;
    __syncthreads();
    if (tid < 32) {
        float v = s_red[tid];
        #pragma unroll
        for (int o = 16; o > 0; o >>= 1)
            v += __shfl_down_sync(0xFFFFFFFFu, v, o);
        if (tid == 0) out[b] = -v;
    }
}

extern "C" void kernel_launch(void* const* d_in, const int* in_sizes, int n_in,
                              void* d_out, int out_size) {
    const float* pred = (const float*)d_in[0];
    const int*   targ = (const int*)d_in[1];
    float*       out  = (float*)d_out;

    const int B  = out_size;                   // j is (B,)
    const int HW = in_sizes[1] / B;            // target is (B,H,W)
    // C = in_sizes[0] / in_sizes[1] == 32 for this problem (design assumes 32)

    const int tilesPerBatch = (HW + TILE - 1) / TILE;
    const int total = B * tilesPerBatch;

    cudaFuncSetAttribute(k_main, cudaFuncAttributeMaxDynamicSharedMemorySize,
                         SMEM_BYTES);

    k_zero<<<4, 256>>>(B * C32 * C32, B * C32);

    dim3 hg(64, B);
    k_hist<<<hg, 256>>>(targ, HW);

    int grid = 444;                            // 148 SMs * 3 blocks
    if (grid > total) grid = total;
    k_main<<<grid, TPB, SMEM_BYTES>>>(pred, targ, B, HW, tilesPerBatch);

    k_final<<<B, C32 * C32>>>(out);
}

// round 17
// speedup vs baseline: 1.6715x; 1.6651x over previous
#include <cuda_runtime.h>

// ---------------------------------------------------------------------------
// JLoss: j[b] = -sum_{i!=k} log(0.5 + 0.5*(S[b,i,i] - S[b,i,k]))
//   S[b,i,k] = (sum over pixels p with target[b,p]==k of pred[b,i,p]) / n_k[b]
//
// Two kernels:
//   k_main : per-block partial T[i][k] + partial n[k]; cp.async double-buffered
//            tile staging, lane==channel segmented reduction, histogram counted
//            in registers (class is warp-uniform).
//   k_final: sum partials, epilogue log + reduce -> out[b]
// ---------------------------------------------------------------------------

#define C32  32
#define TILE 256
#define TPB  256
#define NW   8

// deterministic partials (write-once per slot per call, no zeroing kernel)
__device__ float g_part[512 * 1024];
__device__ int   g_npart[512 * 32];

// dynamic shared layout (floats):
//   [0      , 8192 )  tile buf 0   (32 ch x 256 px, 16B-unit XOR swizzled)
//   [8192   , 16384)  tile buf 1
//   [16384  , 24576)  acc [NW][32][32]   (acc[w][k][i], bank == i)
//   then ints: targ buf0 [256], targ buf1 [256], wcnt [NW*32]
#define SMEM_FLOATS (2 * 8192 + 8192)
#define SMEM_INTS   (2 * TILE + NW * 32)
#define SMEM_BYTES  ((SMEM_FLOATS + SMEM_INTS) * 4)

__device__ __forceinline__ unsigned smem_u32(const void* p) {
    return (unsigned)__cvta_generic_to_shared(p);
}
__device__ __forceinline__ void cpa16(unsigned dst, const void* src) {
    asm volatile("cp.async.cg.shared.global [%0], [%1], 16;\n"
                 :: "r"(dst), "l"(__cvta_generic_to_global(src)));
}
__device__ __forceinline__ void cpa_commit() {
    asm volatile("cp.async.commit_group;\n");
}
template <int N> __device__ __forceinline__ void cpa_wait() {
    asm volatile("cp.async.wait_group %0;\n" :: "n"(N));
}

// Fast staging: full 32x256 tile = 2048 16B units, 8 cp.async per thread.
__device__ __forceinline__ void stage_fast(float* tileb, int* targb,
                                           const float* __restrict__ pb,
                                           const int* __restrict__ tb,
                                           int p0, int HW, int tid) {
    #pragma unroll
    for (int s = tid; s < 2048; s += TPB) {       // 8 iters per thread
        int c = s >> 6, u = s & 63;               // channel, 16B unit in row
        const float* src = pb + (size_t)c * HW + p0 + (u << 2);
        unsigned dst = smem_u32(tileb + c * 256 + ((u ^ (c & 7)) << 2));
        cpa16(dst, src);
    }
    if (tid < 64) {
        cpa16(smem_u32(targb + (tid << 2)), tb + p0 + (tid << 2));
    }
}

// Tail staging (partial tile): scalar with zero fill. Padded pixels get
// value 0 (no sum contribution) and class 0 (count fixed up at flush).
// (Unused for HW divisible by TILE, kept for generality.)
__device__ void stage_tail(float* tileb, int* targb,
                           const float* __restrict__ pb,
                           const int* __restrict__ tb,
                           int p0, int HW, int tid) {
    for (int idx = tid; idx < C32 * TILE; idx += TPB) {
        int c = idx >> 8, j = idx & 255;
        int u = j >> 2, wo = j & 3;
        float v = (p0 + j < HW) ? pb[(size_t)c * HW + p0 + j] : 0.0f;
        tileb[c * 256 + ((u ^ (c & 7)) << 2) + wo] = v;
    }
    targb[tid] = (p0 + tid < HW) ? tb[p0 + tid] : 0;
}

__device__ __forceinline__ void compute_tile(const float* tileb, const int* targb,
                                             float* accw, int lane, int w, int& cnt) {
    const float4* tv = (const float4*)(tileb + lane * 256);  // this lane's channel row
    const int4*   t4 = (const int4*)targb;
    const int sw = lane & 7;
    #pragma unroll
    for (int q = 0; q < 8; ++q) {
        int u = w * 8 + q;                 // 4 pixels per step
        float4 v = tv[u ^ sw];             // conflict-free swizzled LDS.128
        int4   k = t4[u];                  // broadcast (warp-uniform classes)
        accw[k.x * 32] += v.x; cnt += (lane == k.x);
        accw[k.y * 32] += v.y; cnt += (lane == k.y);
        accw[k.z * 32] += v.z; cnt += (lane == k.z);
        accw[k.w * 32] += v.w; cnt += (lane == k.w);
    }
}

__global__ void __launch_bounds__(TPB, 2)
k_main(const float* __restrict__ pred, const int* __restrict__ targ,
       int HW, int GPB, int nT) {
    extern __shared__ float sm[];
    float* s_tile0 = sm;
    float* s_tile1 = sm + 8192;
    float* s_acc   = sm + 16384;                 // [NW][32][32]
    int*   s_targ0 = (int*)(sm + 24576);
    int*   s_targ1 = s_targ0 + TILE;
    int*   s_wcnt  = s_targ1 + TILE;             // [NW][32]

    const int tid = threadIdx.x, w = tid >> 5, lane = tid & 31;
    const int b = blockIdx.x / GPB, g = blockIdx.x % GPB;

    // balanced contiguous tile range within this batch
    const int q0 = nT / GPB, r = nT % GPB;
    const int t0 = g * q0 + (g < r ? g : r);
    const int t1 = t0 + q0 + (g < r ? 1 : 0);

    const float* pb = pred + (size_t)b * C32 * HW;
    const int*   tb = targ + (size_t)b * HW;

    for (int z = tid; z < NW * 1024; z += TPB) s_acc[z] = 0.0f;
    int cnt = 0;
    float* accw = s_acc + w * 1024 + lane;

    // prefetch first tile
    if (t0 < t1) {
        int p0 = t0 * TILE;
        if (p0 + TILE <= HW) stage_fast(s_tile0, s_targ0, pb, tb, p0, HW, tid);
        else                 stage_tail(s_tile0, s_targ0, pb, tb, p0, HW, tid);
        cpa_commit();
    }

    for (int t = t0; t < t1; ++t) {
        const int par = (t - t0) & 1;
        if (t + 1 < t1) {
            int p0 = (t + 1) * TILE;
            float* tl = par ? s_tile0 : s_tile1;
            int*   tg = par ? s_targ0 : s_targ1;
            if (p0 + TILE <= HW) stage_fast(tl, tg, pb, tb, p0, HW, tid);
            else                 stage_tail(tl, tg, pb, tb, p0, HW, tid);
            cpa_commit();
            cpa_wait<1>();            // tile t's group complete
        } else {
            cpa_wait<0>();
        }
        __syncthreads();
        compute_tile(par ? s_tile1 : s_tile0, par ? s_targ1 : s_targ0,
                     accw, lane, w, cnt);
        __syncthreads();
    }

    // flush deterministic partials (transpose acc[k][i] -> T[i][k])
    s_wcnt[w * 32 + lane] = cnt;
    __syncthreads();
    for (int kk = tid; kk < 1024; kk += TPB) {
        float s = 0.0f;
        #pragma unroll
        for (int ww = 0; ww < NW; ++ww) s += s_acc[ww * 1024 + kk];
        int k = kk >> 5, i = kk & 31;
        g_part[(size_t)blockIdx.x * 1024 + i * 32 + k] = s;
    }
    if (tid < 32) {
        int n = 0;
        #pragma unroll
        for (int ww = 0; ww < NW; ++ww) n += s_wcnt[ww * 32 + tid];
        if (tid == 0 && t1 == nT) n -= nT * TILE - HW;  // padded px counted as class 0
        g_npart[blockIdx.x * 32 + tid] = n;
    }
}

__global__ void k_final(float* __restrict__ out, int GPB) {
    const int b = blockIdx.x, tid = threadIdx.x;   // 1024 threads
    const int i = tid >> 5, k = tid & 31;

    __shared__ float s_n[C32], s_diag[C32], s_red[C32];

    if (tid < 32) {
        int n = 0;
        for (int g = 0; g < GPB; ++g) n += g_npart[(b * GPB + g) * 32 + tid];
        s_n[tid] = (float)n;
    }
    float T = 0.0f;
    for (int g = 0; g < GPB; ++g)
        T += g_part[(size_t)(b * GPB + g) * 1024 + tid];   // (i*32+k) layout
    __syncthreads();

    float S = T / s_n[k];
    if (i == k) s_diag[i] = S;
    __syncthreads();

    float term = (i != k) ? logf(0.5f + 0.5f * (s_diag[i] - S)) : 0.0f;
    #pragma unroll
    for (int o = 16; o > 0; o >>= 1)
        term += __shfl_down_sync(0xFFFFFFFFu, term, o);
    if (k == 0) s_red[i] = term;
    __syncthreads();
    if (tid < 32) {
        float v = s_red[tid];
        #pragma unroll
        for (int o = 16; o > 0; o >>= 1)
            v += __shfl_down_sync(0xFFFFFFFFu, v, o);
        if (tid == 0) out[b] = -v;
    }
}

extern "C" void kernel_launch(void* const* d_in, const int* in_sizes, int n_in,
                              void* d_out, int out_size) {
    const float* pred = (const float*)d_in[0];
    const int*   targ = (const int*)d_in[1];
    float*       out  = (float*)d_out;

    const int B  = out_size;                 // j is (B,)
    const int HW = in_sizes[1] / B;          // target is (B,H,W)
    const int nT = (HW + TILE - 1) / TILE;

    // one full wave at 2 blocks/SM: grid = B * GPB ~ 296 (and fits g_part)
    int GPB = 296 / B;
    if (GPB < 1) GPB = 1;
    if (GPB > nT) GPB = nT;
    if (GPB > 512 / B) GPB = 512 / B;

    cudaFuncSetAttribute(k_main, cudaFuncAttributeMaxDynamicSharedMemorySize,
                         SMEM_BYTES);

    k_main<<<B * GPB, TPB, SMEM_BYTES>>>(pred, targ, HW, GPB, nT);
    k_final<<<B, 1024>>>(out, GPB);
}